// round 12
// baseline (speedup 1.0000x reference)
#include <cuda_runtime.h>
#include <stdint.h>

#define X_COORD_START 10
#define Y_COORD_START 21
#define EOS_TOKEN     39
#define MAX_REACH     5.0f
#define WINDOW_SIZE   4
#define PENALTY_SCALE 1.0f

#define ROW_LEN      2048   // tokens per row (8 KB)
#define ROWS_PER_CTA 4
#define NTHREADS     128    // 4 warps per CTA
#define NBUF         3      // cp.async row buffers
#define WCHUNKS      4      // int4 chunks per warp per row
#define SEGSTRIDE    260    // 4 halo slots + up to 256 compacted pairs
#define NBUCKETS     64
#define BSTRIDE      32     // doubles: 256B apart
#define ISTRIDE      64     // ints: 256B apart

// Bucketed self-resetting scratch (zeroed at load; last CTA resets per launch).
__device__ double        g_bt[NBUCKETS * BSTRIDE];
__device__ int           g_bn[NBUCKETS * ISTRIDE];
__device__ unsigned int  g_counter = 0;

__device__ __forceinline__ bool is_valid(int x, int y) {
    return ((unsigned)(x - X_COORD_START) < (unsigned)(Y_COORD_START - X_COORD_START)) &
           ((unsigned)(y - Y_COORD_START) < (unsigned)(EOS_TOKEN - Y_COORD_START));
}

__global__ __launch_bounds__(NTHREADS, 8)
void reach_loss_stream(const int* __restrict__ in, float* __restrict__ out,
                       int n_ctas) {
    const int t    = threadIdx.x;
    const int lane = t & 31;
    const int wid  = t >> 5;          // 0..3
    const unsigned lt = (1u << lane) - 1u;

    __shared__ int    raw[NBUF][ROW_LEN];     // 24 KB streamed rows
    __shared__ int    seg[4 * SEGSTRIDE];     // warp-private compacted segments
    __shared__ int    scnt[4];
    __shared__ float  wpart[4];
    __shared__ int    s_last;
    __shared__ double s_red[2];

    const size_t gbase = (size_t)blockIdx.x * ROWS_PER_CTA * ROW_LEN;
    const unsigned raw_base = (unsigned)__cvta_generic_to_shared(&raw[0][0]);

    // ---- Prologue: issue rows 0..NBUF-1 (one commit group each) ----
    #pragma unroll
    for (int r = 0; r < NBUF; r++) {
        #pragma unroll
        for (int it = 0; it < ROW_LEN / (4 * NTHREADS); it++) {
            const int idx = it * NTHREADS + t;                  // int4 index
            const unsigned dst = raw_base + (unsigned)(r * ROW_LEN * 4 + idx * 16);
            const int* src = in + gbase + (size_t)r * ROW_LEN + 4 * idx;
            asm volatile("cp.async.cg.shared.global [%0], [%1], 16;\n"
                         :: "r"(dst), "l"(src));
        }
        asm volatile("cp.async.commit_group;\n");
    }

    double acc = 0.0;   // thread 0 only
    int    nvs = 0;

    #pragma unroll
    for (int r = 0; r < ROWS_PER_CTA; r++) {
        // Wait until row r's group is complete (constants resolve per unrolled r)
        if (r <= ROWS_PER_CTA - NBUF)      asm volatile("cp.async.wait_group %0;\n" :: "n"(NBUF - 1));
        else if (r == ROWS_PER_CTA - 2)    asm volatile("cp.async.wait_group 1;\n");
        else                               asm volatile("cp.async.wait_group 0;\n");
        __syncthreads();   // data visible to all threads; prior buf reads fenced

        const int buf = r % NBUF;
        const int4* raw4 = reinterpret_cast<const int4*>(raw[buf]);

        // ---- Single-pass ballot compaction into warp-private segment ----
        int* myseg = &seg[wid * SEGSTRIDE];
        int cnt = 0;
        #pragma unroll
        for (int c = 0; c < WCHUNKS; c++) {
            const int q = (wid * WCHUNKS + c) * 32 + lane;
            const int4 p = raw4[q];
            const bool va = (q != 0) && is_valid(p.x, p.y);
            const bool vb = is_valid(p.z, p.w);
            const unsigned bA = __ballot_sync(0xffffffffu, va);
            const unsigned bB = __ballot_sync(0xffffffffu, vb);
            const int pos = cnt + __popc(bA & lt) + __popc(bB & lt);
            if (va) myseg[4 + pos]            = (p.y << 16) | p.x;
            if (vb) myseg[4 + pos + (va?1:0)] = (p.w << 16) | p.z;
            cnt += __popc(bA) + __popc(bB);
        }
        if (lane == 0) scnt[wid] = cnt;
        __syncthreads();   // compaction done => raw[buf] is free

        // Refill the freed buffer with row r+NBUF (keeps loads streaming)
        if (r + NBUF < ROWS_PER_CTA) {
            #pragma unroll
            for (int it = 0; it < ROW_LEN / (4 * NTHREADS); it++) {
                const int idx = it * NTHREADS + t;
                const unsigned dst = raw_base + (unsigned)(buf * ROW_LEN * 4 + idx * 16);
                const int* src = in + gbase + (size_t)(r + NBUF) * ROW_LEN + 4 * idx;
                asm volatile("cp.async.cg.shared.global [%0], [%1], 16;\n"
                             :: "r"(dst), "l"(src));
            }
            asm volatile("cp.async.commit_group;\n");
        }

        const int s0 = scnt[0], s1 = scnt[1], s2 = scnt[2], s3 = scnt[3];
        const int prefix = (wid > 0 ? s0 : 0) + (wid > 1 ? s1 : 0)
                         + (wid > 2 ? s2 : 0);
        const int total = s0 + s1 + s2 + s3;

        // ---- Halo: lanes 0..3 fetch the 4 global predecessors ----
        if (lane < 4) {
            const int gb = prefix - 1 - lane;
            if (gb >= 0) {
                int w2, loc;
                if      (gb >= s0 + s1 + s2) { w2 = 3; loc = gb - (s0 + s1 + s2); }
                else if (gb >= s0 + s1)      { w2 = 2; loc = gb - (s0 + s1); }
                else if (gb >= s0)           { w2 = 1; loc = gb - s0; }
                else                         { w2 = 0; loc = gb; }
                myseg[3 - lane] = seg[w2 * SEGSTRIDE + 4 + loc];
            }
        }
        __syncwarp();

        // ---- Uniform window loop over this warp's local pairs ----
        const int* s = myseg + 4;
        const int st = (4 - prefix) > 0 ? (4 - prefix) : 0;
        float vsum = 0.0f;
        for (int i = st + lane; i < cnt; i += 32) {
            const int pki = s[i];
            const int xi = pki & 0xffff;
            const int yi = pki >> 16;
            int msq = 0x7fffffff;
            #pragma unroll
            for (int j = 1; j <= WINDOW_SIZE; j++) {
                const int pkj = s[i - j];
                const int dx = xi - (pkj & 0xffff);
                const int dy = yi - (pkj >> 16);
                msq = min(msq, dx * dx + dy * dy);
            }
            vsum += fmaxf(sqrtf((float)msq) - MAX_REACH, 0.0f);
        }
        #pragma unroll
        for (int o = 16; o > 0; o >>= 1)
            vsum += __shfl_xor_sync(0xffffffffu, vsum, o);
        if (lane == 0) wpart[wid] = vsum;
        __syncthreads();

        if (t == 0 && total >= WINDOW_SIZE + 1) {
            const float pen = wpart[0] + wpart[1] + wpart[2] + wpart[3];
            acc += (double)(pen / (float)(total - WINDOW_SIZE));
            nvs += 1;
        }
        // next iteration's post-wait __syncthreads fences seg/scnt/wpart reuse
    }

    // ---- Bucketed fire-and-forget accumulation + single ticket ----
    __syncthreads();
    if (t == 0) {
        const int b = blockIdx.x & (NBUCKETS - 1);
        if (nvs) {
            atomicAdd(&g_bt[b * BSTRIDE], acc);   // RED (no return)
            atomicAdd(&g_bn[b * ISTRIDE], nvs);   // RED
        }
        __threadfence();
        const unsigned ticket = atomicAdd(&g_counter, 1u);
        s_last = (ticket == (unsigned)(n_ctas - 1)) ? 1 : 0;
    }
    __syncthreads();

    // ---- Parallel finalize + reset by the last CTA ----
    if (s_last) {
        double bt = 0.0;
        int    bn = 0;
        if (t < NBUCKETS) {
            bt = *((volatile double*)&g_bt[t * BSTRIDE]);
            bn = *((volatile int*)&g_bn[t * ISTRIDE]);
            g_bt[t * BSTRIDE] = 0.0;
            g_bn[t * ISTRIDE] = 0;
        }
        #pragma unroll
        for (int o = 16; o > 0; o >>= 1) {
            bt += __shfl_xor_sync(0xffffffffu, bt, o);
            bn += __shfl_xor_sync(0xffffffffu, bn, o);
        }
        if (t == 0)  { s_red[0] = bt; wpart[0] = (float)bn; }
        if (t == 32) { s_red[1] = bt; wpart[1] = (float)bn; }
        __syncthreads();
        if (t == 0) {
            const double tot = s_red[0] + s_red[1];
            const int    tn  = (int)wpart[0] + (int)wpart[1];
            out[0] = (tn > 0) ? (float)(PENALTY_SCALE * tot / (double)tn) : 0.0f;
            __threadfence();
            g_counter = 0u;
        }
    }
}

extern "C" void kernel_launch(void* const* d_in, const int* in_sizes, int n_in,
                              void* d_out, int out_size) {
    (void)n_in; (void)out_size;
    const int* in = (const int*)d_in[0];
    const int B = in_sizes[0] / ROW_LEN;            // 2048 rows
    const int n_ctas = B / ROWS_PER_CTA;            // 512 CTAs
    reach_loss_stream<<<n_ctas, NTHREADS>>>(in, (float*)d_out, n_ctas);
}

// round 13
// speedup vs baseline: 1.1229x; 1.1229x over previous
#include <cuda_runtime.h>
#include <stdint.h>

#define X_COORD_START 10
#define Y_COORD_START 21
#define EOS_TOKEN     39
#define MAX_REACH     5.0f
#define WINDOW_SIZE   4
#define PENALTY_SCALE 1.0f

#define ROW_LEN   2048   // tokens per row
#define NTHREADS  128    // 4 warps, one row per CTA
#define WCHUNKS   4      // int4 chunks per warp
#define WSEGCAP   256    // max valid pairs per warp quarter
#define NBUCKETS  64
#define BSTRIDE   32     // doubles: 256B apart
#define ISTRIDE   64     // ints: 256B apart

// Bucketed self-resetting scratch (zeroed at load; last CTA resets per launch).
__device__ double        g_bt[NBUCKETS * BSTRIDE];
__device__ int           g_bn[NBUCKETS * ISTRIDE];
__device__ unsigned int  g_counter = 0;

__device__ __forceinline__ bool is_valid(int x, int y) {
    return ((unsigned)(x - X_COORD_START) < (unsigned)(Y_COORD_START - X_COORD_START)) &
           ((unsigned)(y - Y_COORD_START) < (unsigned)(EOS_TOKEN - Y_COORD_START));
}

// packed byte coords: b0 = x-10 (0..10), b1 = y-20 (1..18), b2=b3=0
__device__ __forceinline__ unsigned short pack_pair(int x, int y) {
    return (unsigned short)((x - X_COORD_START) | ((y - (Y_COORD_START - 1)) << 8));
}

__global__ __launch_bounds__(NTHREADS, 12)
void reach_loss_simd(const int* __restrict__ in, float* __restrict__ out,
                     int n_ctas) {
    const int t    = threadIdx.x;
    const int lane = t & 31;
    const int wid  = t >> 5;          // 0..3
    const unsigned lt = (1u << lane) - 1u;

    __shared__ unsigned short wseg[4][WSEGCAP];  // per-warp private compaction
    __shared__ unsigned short buf[1028];          // contiguous compacted row
    __shared__ int    scnt[4];
    __shared__ float  wpart[4];
    __shared__ int    s_last;
    __shared__ double s_red[2];

    const int* rowp = in + (size_t)blockIdx.x * ROW_LEN;

    // ---- Load this warp's quarter row: 4 independent LDG.128 ----
    int4 v[WCHUNKS];
    #pragma unroll
    for (int c = 0; c < WCHUNKS; c++)
        v[c] = reinterpret_cast<const int4*>(rowp)[(wid * WCHUNKS + c) * 32 + lane];

    // ---- Single-pass ballot compaction into warp-private segment ----
    // int4 q holds pair A = 2q-1 (tokens 4q,4q+1; q>=1) and pair B = 2q.
    int cnt = 0;
    #pragma unroll
    for (int c = 0; c < WCHUNKS; c++) {
        const int4 p = v[c];
        const int q = (wid * WCHUNKS + c) * 32 + lane;
        const bool va = (q != 0) && is_valid(p.x, p.y);
        const bool vb = is_valid(p.z, p.w);
        const unsigned bA = __ballot_sync(0xffffffffu, va);
        const unsigned bB = __ballot_sync(0xffffffffu, vb);
        const int pos = cnt + __popc(bA & lt) + __popc(bB & lt);
        if (va) wseg[wid][pos]            = pack_pair(p.x, p.y);
        if (vb) wseg[wid][pos + (va?1:0)] = pack_pair(p.z, p.w);
        cnt += __popc(bA) + __popc(bB);
    }
    if (lane == 0) scnt[wid] = cnt;
    __syncthreads();

    const int s0 = scnt[0], s1 = scnt[1], s2 = scnt[2], s3 = scnt[3];
    const int p1 = s0, p2 = s0 + s1, p3 = s0 + s1 + s2;
    const int total = p3 + s3;

    // ---- Copy pass: merge 4 segments into one contiguous buffer ----
    for (int i = t; i < total; i += NTHREADS) {
        const int w = (i >= p1) + (i >= p2) + (i >= p3);
        const int base = (w == 0) ? 0 : (w == 1) ? p1 : (w == 2) ? p2 : p3;
        buf[i] = wseg[w][i - base];
    }
    __syncthreads();

    // ---- Balanced window loop: SIMD byte distances + approx sqrt ----
    float vsum = 0.0f;
    for (int i = WINDOW_SIZE + t; i < total; i += NTHREADS) {
        const int ci = (int)buf[i];       // bytes: (dx, dy, 0, 0)
        int msq = 0x7fffffff;
        #pragma unroll
        for (int j = 1; j <= WINDOW_SIZE; j++) {
            const int cj = (int)buf[i - j];
            const int d  = __vsub4(ci, cj);      // per-byte diff (s8 wrap)
            msq = min(msq, __dp4a(d, d, 0));     // dx*dx + dy*dy
        }
        float sd;
        asm("sqrt.approx.f32 %0, %1;" : "=f"(sd) : "f"((float)msq));
        vsum += fmaxf(sd - MAX_REACH, 0.0f);     // exact 0 when msq <= 25
    }
    #pragma unroll
    for (int o = 16; o > 0; o >>= 1)
        vsum += __shfl_xor_sync(0xffffffffu, vsum, o);
    if (lane == 0) wpart[wid] = vsum;
    __syncthreads();

    // ---- Bucketed fire-and-forget accumulation + single ticket ----
    if (t == 0) {
        const int b = blockIdx.x & (NBUCKETS - 1);
        if (total >= WINDOW_SIZE + 1) {
            const float pen = wpart[0] + wpart[1] + wpart[2] + wpart[3];
            atomicAdd(&g_bt[b * BSTRIDE],
                      (double)(pen / (float)(total - WINDOW_SIZE)));  // RED
            atomicAdd(&g_bn[b * ISTRIDE], 1);                          // RED
        }
        __threadfence();
        const unsigned ticket = atomicAdd(&g_counter, 1u);
        s_last = (ticket == (unsigned)(n_ctas - 1)) ? 1 : 0;
    }
    __syncthreads();

    // ---- Parallel finalize + reset by the last CTA ----
    if (s_last) {
        double bt = 0.0;
        int    bn = 0;
        if (t < NBUCKETS) {
            bt = *((volatile double*)&g_bt[t * BSTRIDE]);
            bn = *((volatile int*)&g_bn[t * ISTRIDE]);
            g_bt[t * BSTRIDE] = 0.0;
            g_bn[t * ISTRIDE] = 0;
        }
        #pragma unroll
        for (int o = 16; o > 0; o >>= 1) {
            bt += __shfl_xor_sync(0xffffffffu, bt, o);
            bn += __shfl_xor_sync(0xffffffffu, bn, o);
        }
        if (t == 0)  { s_red[0] = bt; wpart[0] = (float)bn; }
        if (t == 32) { s_red[1] = bt; wpart[1] = (float)bn; }
        __syncthreads();
        if (t == 0) {
            const double tot = s_red[0] + s_red[1];
            const int    tn  = (int)wpart[0] + (int)wpart[1];
            out[0] = (tn > 0) ? (float)(PENALTY_SCALE * tot / (double)tn) : 0.0f;
            __threadfence();
            g_counter = 0u;
        }
    }
}

extern "C" void kernel_launch(void* const* d_in, const int* in_sizes, int n_in,
                              void* d_out, int out_size) {
    (void)n_in; (void)out_size;
    const int* in = (const int*)d_in[0];
    const int B = in_sizes[0] / ROW_LEN;   // 2048 rows = 2048 CTAs
    reach_loss_simd<<<B, NTHREADS>>>(in, (float*)d_out, B);
}

// round 14
// speedup vs baseline: 1.1837x; 1.0542x over previous
#include <cuda_runtime.h>
#include <stdint.h>

#define X_COORD_START 10
#define Y_COORD_START 21
#define EOS_TOKEN     39
#define MAX_REACH     5.0f
#define WINDOW_SIZE   4
#define PENALTY_SCALE 1.0f

#define ROW_LEN      2048   // tokens per row
#define ROWS_PER_CTA 2
#define NTHREADS     128    // 4 warps
#define WCHUNKS      4      // int4 chunks per warp per row
#define WSEGCAP      256
#define NBUCKETS     64
#define BSTRIDE      32     // doubles: 256B apart
#define ISTRIDE      64     // ints: 256B apart

// Bucketed self-resetting scratch (zeroed at load; last CTA resets per launch).
__device__ double        g_bt[NBUCKETS * BSTRIDE];
__device__ int           g_bn[NBUCKETS * ISTRIDE];
__device__ unsigned int  g_counter = 0;

__device__ __forceinline__ bool is_valid(int x, int y) {
    return ((unsigned)(x - X_COORD_START) < (unsigned)(Y_COORD_START - X_COORD_START)) &
           ((unsigned)(y - Y_COORD_START) < (unsigned)(EOS_TOKEN - Y_COORD_START));
}

// packed byte coords: b0 = x-10 (0..10), b1 = y-20 (1..18)
__device__ __forceinline__ unsigned short pack_pair(int x, int y) {
    return (unsigned short)((x - X_COORD_START) | ((y - (Y_COORD_START - 1)) << 8));
}

__global__ __launch_bounds__(NTHREADS, 8)
void reach_loss_hybrid(const int* __restrict__ in, float* __restrict__ out,
                       int n_ctas) {
    const int t    = threadIdx.x;
    const int lane = t & 31;
    const int wid  = t >> 5;          // 0..3
    const unsigned lt = (1u << lane) - 1u;

    __shared__ unsigned short wseg[4][WSEGCAP];  // per-warp compaction
    __shared__ unsigned short buf[1028];          // contiguous compacted row
    __shared__ int    scnt[4];
    __shared__ float  wpart[4];
    __shared__ int    s_last;
    __shared__ double s_red[2];

    const int row0 = blockIdx.x * ROWS_PER_CTA;

    // Prologue: load row 0 into registers (warp w: int4 indices (w*4+c)*32+lane)
    int4 v[WCHUNKS], vn[WCHUNKS];
    #pragma unroll
    for (int c = 0; c < WCHUNKS; c++)
        v[c] = reinterpret_cast<const int4*>(in + (size_t)row0 * ROW_LEN)
                   [(wid * WCHUNKS + c) * 32 + lane];

    float acc = 0.0f;   // thread 0 only: sum of normalized per-row penalties
    int   nvs = 0;

    #pragma unroll
    for (int r = 0; r < ROWS_PER_CTA; r++) {
        // Issue next row's loads NOW — latency hides under this row's work.
        if (r + 1 < ROWS_PER_CTA) {
            #pragma unroll
            for (int c = 0; c < WCHUNKS; c++)
                vn[c] = reinterpret_cast<const int4*>(
                            in + (size_t)(row0 + r + 1) * ROW_LEN)
                            [(wid * WCHUNKS + c) * 32 + lane];
        }

        // ---- Single-pass ballot compaction into warp-private segment ----
        // int4 q holds pair A = 2q-1 (tokens 4q,4q+1; q>=1) and pair B = 2q.
        int cnt = 0;
        #pragma unroll
        for (int c = 0; c < WCHUNKS; c++) {
            const int4 p = v[c];
            const int q = (wid * WCHUNKS + c) * 32 + lane;
            const bool va = (q != 0) && is_valid(p.x, p.y);
            const bool vb = is_valid(p.z, p.w);
            const unsigned bA = __ballot_sync(0xffffffffu, va);
            const unsigned bB = __ballot_sync(0xffffffffu, vb);
            const int pos = cnt + __popc(bA & lt) + __popc(bB & lt);
            if (va) wseg[wid][pos]            = pack_pair(p.x, p.y);
            if (vb) wseg[wid][pos + (va?1:0)] = pack_pair(p.z, p.w);
            cnt += __popc(bA) + __popc(bB);
        }
        if (lane == 0) scnt[wid] = cnt;
        __syncthreads();

        const int s0 = scnt[0], s1 = scnt[1], s2 = scnt[2], s3 = scnt[3];
        const int p1 = s0, p2 = s0 + s1, p3 = s0 + s1 + s2;
        const int total = p3 + s3;

        // ---- Merge the 4 segments into one contiguous buffer ----
        for (int i = t; i < total; i += NTHREADS) {
            const int w = (i >= p1) + (i >= p2) + (i >= p3);
            const int base = (w == 0) ? 0 : (w == 1) ? p1 : (w == 2) ? p2 : p3;
            buf[i] = wseg[w][i - base];
        }
        __syncthreads();

        // ---- Balanced window loop: SIMD byte distances + approx sqrt ----
        float vsum = 0.0f;
        for (int i = WINDOW_SIZE + t; i < total; i += NTHREADS) {
            const int ci = (int)buf[i];
            int msq = 0x7fffffff;
            #pragma unroll
            for (int j = 1; j <= WINDOW_SIZE; j++) {
                const int cj = (int)buf[i - j];
                const int d  = __vsub4(ci, cj);
                msq = min(msq, __dp4a(d, d, 0));
            }
            float sd;
            asm("sqrt.approx.f32 %0, %1;" : "=f"(sd) : "f"((float)msq));
            vsum += fmaxf(sd - MAX_REACH, 0.0f);   // exact 0 when msq <= 25
        }
        #pragma unroll
        for (int o = 16; o > 0; o >>= 1)
            vsum += __shfl_xor_sync(0xffffffffu, vsum, o);
        if (lane == 0) wpart[wid] = vsum;
        __syncthreads();

        if (t == 0 && total >= WINDOW_SIZE + 1) {
            const float pen = wpart[0] + wpart[1] + wpart[2] + wpart[3];
            acc += pen / (float)(total - WINDOW_SIZE);
            nvs += 1;
        }
        if (r + 1 < ROWS_PER_CTA) {
            __syncthreads();   // wseg/scnt/wpart reuse next row
            #pragma unroll
            for (int c = 0; c < WCHUNKS; c++) v[c] = vn[c];
        }
    }

    // ---- Bucketed fire-and-forget accumulation + single ticket ----
    if (t == 0) {
        const int b = blockIdx.x & (NBUCKETS - 1);
        if (nvs) {
            atomicAdd(&g_bt[b * BSTRIDE], (double)acc);  // RED (no return)
            atomicAdd(&g_bn[b * ISTRIDE], nvs);          // RED
        }
        __threadfence();
        const unsigned ticket = atomicAdd(&g_counter, 1u);
        s_last = (ticket == (unsigned)(n_ctas - 1)) ? 1 : 0;
    }
    __syncthreads();

    // ---- Parallel finalize + reset by the last CTA ----
    if (s_last) {
        double bt = 0.0;
        int    bn = 0;
        if (t < NBUCKETS) {
            bt = *((volatile double*)&g_bt[t * BSTRIDE]);
            bn = *((volatile int*)&g_bn[t * ISTRIDE]);
            g_bt[t * BSTRIDE] = 0.0;
            g_bn[t * ISTRIDE] = 0;
        }
        #pragma unroll
        for (int o = 16; o > 0; o >>= 1) {
            bt += __shfl_xor_sync(0xffffffffu, bt, o);
            bn += __shfl_xor_sync(0xffffffffu, bn, o);
        }
        if (t == 0)  { s_red[0] = bt; wpart[0] = (float)bn; }
        if (t == 32) { s_red[1] = bt; wpart[1] = (float)bn; }
        __syncthreads();
        if (t == 0) {
            const double tot = s_red[0] + s_red[1];
            const int    tn  = (int)wpart[0] + (int)wpart[1];
            out[0] = (tn > 0) ? (float)(PENALTY_SCALE * tot / (double)tn) : 0.0f;
            __threadfence();
            g_counter = 0u;
        }
    }
}

extern "C" void kernel_launch(void* const* d_in, const int* in_sizes, int n_in,
                              void* d_out, int out_size) {
    (void)n_in; (void)out_size;
    const int* in = (const int*)d_in[0];
    const int B = in_sizes[0] / ROW_LEN;            // 2048 rows
    const int n_ctas = B / ROWS_PER_CTA;            // 1024 CTAs
    reach_loss_hybrid<<<n_ctas, NTHREADS>>>(in, (float*)d_out, n_ctas);
}